// round 2
// baseline (speedup 1.0000x reference)
#include <cuda_runtime.h>
#include <math.h>
#include <stdint.h>

#define G 64
#define NN 1000
#define EE 8192
#define C 128
#define HIDN 256
#define NCLS 2

// ---------------- scratch (device globals; no allocation allowed) ----------------
__device__ float g_bufA[(size_t)G * NN * C];   // 32.8 MB
__device__ float g_bufB[(size_t)G * NN * C];   // 32.8 MB
__device__ float g_dinv[G * NN];
__device__ int   g_rowptr[G * (NN + 1)];
__device__ int   g_csrsrc[G * EE];
__device__ float g_gvec[G * C];
__device__ float g_qkv[G * 3 * C];
__device__ float g_nrepr[C];

// ---------------- fused graph prep: one block per graph ----------------
__global__ void prep_kernel(const int* __restrict__ ei) {
    __shared__ int cnt[1024];
    __shared__ int cur[NN];
    int g = blockIdx.x;
    int t = threadIdx.x;          // 1024 threads
    const int* eb = ei + (size_t)g * 2 * EE;

    cnt[t] = 0;
    __syncthreads();
    // count degrees (dst half)
    for (int e = t; e < EE; e += 1024) atomicAdd(&cnt[eb[EE + e]], 1);
    __syncthreads();
    int d = cnt[t];
    __syncthreads();
    // inclusive scan in place
    for (int off = 1; off < 1024; off <<= 1) {
        int v = (t >= off) ? cnt[t - off] : 0;
        __syncthreads();
        cnt[t] += v;
        __syncthreads();
    }
    if (t < NN) {
        g_rowptr[g * (NN + 1) + t + 1] = cnt[t];
        cur[t] = cnt[t] - d;
        g_dinv[g * NN + t] = rsqrtf((float)d + 1.0f);
    }
    if (t == 0) g_rowptr[g * (NN + 1)] = 0;
    if (g == 0 && t < C) g_nrepr[t] = 0.0f;
    __syncthreads();
    // CSR fill via smem cursors
    for (int e = t; e < EE; e += 1024) {
        int src = eb[e];
        int dst = eb[EE + e];
        int pos = atomicAdd(&cur[dst], 1);
        g_csrsrc[g * EE + pos] = src;
    }
}

// ---------------- tf32 tensor-core GEMM (3xTF32): (64000 x 128) @ (128 x 128) ----------------
__device__ __forceinline__ uint32_t f2tf32(float f) {
    uint32_t u;
    asm("cvt.rna.tf32.f32 %0, %1;" : "=r"(u) : "f"(f));
    return u;
}

#define MMA_TF32(d0,d1,d2,d3,a0,a1,a2,a3,b0,b1)                              \
    asm volatile(                                                            \
        "mma.sync.aligned.m16n8k8.row.col.f32.tf32.tf32.f32 "                \
        "{%0,%1,%2,%3}, {%4,%5,%6,%7}, {%8,%9}, {%0,%1,%2,%3};\n"            \
        : "+f"(d0), "+f"(d1), "+f"(d2), "+f"(d3)                             \
        : "r"(a0), "r"(a1), "r"(a2), "r"(a3), "r"(b0), "r"(b1))

#define WPAD 132
// smem words: W big + W small (128*132 each), X big + X small (64*132 each)
#define GEMM_SMEM_WORDS ((2 * 128 + 2 * 64) * WPAD)

__global__ void __launch_bounds__(256, 1)
gemm_tc_kernel(const float* __restrict__ X, const float* __restrict__ W,
               float* __restrict__ Y) {
    extern __shared__ uint32_t usm[];
    uint32_t* Wb = usm;                         // [128][132]
    uint32_t* Wsm = Wb + 128 * WPAD;
    uint32_t* Xb = Wsm + 128 * WPAD;            // [64][132]
    uint32_t* Xsm = Xb + 64 * WPAD;

    int tid = threadIdx.x;
    int warp = tid >> 5, lane = tid & 31;
    int rowBase = blockIdx.x * 64;

    // stage W (tf32 big + residual)
    for (int i = tid; i < 128 * 128; i += 256) {
        int r = i >> 7, c = i & 127;
        float v = W[i];
        uint32_t b = f2tf32(v);
        Wb[r * WPAD + c] = b;
        Wsm[r * WPAD + c] = f2tf32(v - __uint_as_float(b));
    }
    // stage X rows
    for (int i = tid; i < 64 * 128; i += 256) {
        int r = i >> 7, c = i & 127;
        float v = X[(size_t)(rowBase + r) * C + c];
        uint32_t b = f2tf32(v);
        Xb[r * WPAD + c] = b;
        Xsm[r * WPAD + c] = f2tf32(v - __uint_as_float(b));
    }
    __syncthreads();

    int grp = lane >> 2, tig = lane & 3;
    int cb = warp * 16;                         // this warp's 16 output cols

    // preload A = W^T fragments (16 k-steps, big + small)
    uint32_t ab[16][4], as[16][4];
#pragma unroll
    for (int ks = 0; ks < 16; ks++) {
        int k0 = 8 * ks + tig;
        ab[ks][0] = Wb[k0 * WPAD + cb + grp];
        ab[ks][1] = Wb[k0 * WPAD + cb + grp + 8];
        ab[ks][2] = Wb[(k0 + 4) * WPAD + cb + grp];
        ab[ks][3] = Wb[(k0 + 4) * WPAD + cb + grp + 8];
        as[ks][0] = Wsm[k0 * WPAD + cb + grp];
        as[ks][1] = Wsm[k0 * WPAD + cb + grp + 8];
        as[ks][2] = Wsm[(k0 + 4) * WPAD + cb + grp];
        as[ks][3] = Wsm[(k0 + 4) * WPAD + cb + grp + 8];
    }

    for (int rt = 0; rt < 8; rt++) {
        float d0 = 0.f, d1 = 0.f, d2 = 0.f, d3 = 0.f;
        int xrow = (rt * 8 + grp) * WPAD;
#pragma unroll
        for (int ks = 0; ks < 16; ks++) {
            uint32_t bb0 = Xb[xrow + 8 * ks + tig];
            uint32_t bb1 = Xb[xrow + 8 * ks + tig + 4];
            uint32_t bs0 = Xsm[xrow + 8 * ks + tig];
            uint32_t bs1 = Xsm[xrow + 8 * ks + tig + 4];
            MMA_TF32(d0, d1, d2, d3, ab[ks][0], ab[ks][1], ab[ks][2], ab[ks][3], bb0, bb1);
            MMA_TF32(d0, d1, d2, d3, as[ks][0], as[ks][1], as[ks][2], as[ks][3], bb0, bb1);
            MMA_TF32(d0, d1, d2, d3, ab[ks][0], ab[ks][1], ab[ks][2], ab[ks][3], bs0, bs1);
        }
        // D layout: d0:(col cb+grp, row 2*tig), d1:(row 2*tig+1), d2/d3: col +8
        int r0 = rowBase + rt * 8 + 2 * tig;
        Y[(size_t)r0 * C + cb + grp] = d0;
        Y[(size_t)(r0 + 1) * C + cb + grp] = d1;
        Y[(size_t)r0 * C + cb + grp + 8] = d2;
        Y[(size_t)(r0 + 1) * C + cb + grp + 8] = d3;
    }
}

// ---------------- smem-tiled aggregation: block = (chunk of 32 cols, graph) ----------------
// LAYER 0: out = tanh(agg) written to `out` (full rows)
// LAYER 1: graph-sum of tanh(agg) written straight to g_gvec (no row output)
#define AGG_SMEM_BYTES ((NN * 32 + NN + 1024) * 4 + (NN + 1 + EE + 3) * 4)

template <int LAYER>
__global__ void __launch_bounds__(1024, 1)
agg_kernel(const float* __restrict__ h, float* __restrict__ out,
           const float* __restrict__ bias) {
    extern __shared__ float sm[];
    float* htile = sm;                       // [1000][32]
    float* dinv_s = sm + NN * 32;            // [1000]
    float* wsum = dinv_s + NN;               // [32][32]
    int* rowptr_s = (int*)(wsum + 1024);     // [1001]
    int* src_s = rowptr_s + NN + 1 + 3;      // [8192] (padded for alignment)

    int g = blockIdx.y;
    int c0 = blockIdx.x * 32;
    int tid = threadIdx.x;
    int warp = tid >> 5, lane = tid & 31;

    // fill tile + graph metadata
    for (int r = warp; r < NN; r += 32)
        htile[r * 32 + lane] = h[((size_t)g * NN + r) * C + c0 + lane];
    for (int i = tid; i < NN; i += 1024) dinv_s[i] = g_dinv[g * NN + i];
    for (int i = tid; i < NN + 1; i += 1024) rowptr_s[i] = g_rowptr[g * (NN + 1) + i];
    for (int i = tid; i < EE; i += 1024) src_s[i] = g_csrsrc[g * EE + i];
    float bia = bias[c0 + lane];
    __syncthreads();

    float gacc = 0.0f;
    for (int n = warp; n < NN; n += 32) {
        int st = rowptr_s[n];
        int en = rowptr_s[n + 1];
        float dn = dinv_s[n];
        float acc = htile[n * 32 + lane] * dn * dn;
        for (int e = st; e < en; e++) {
            int s = src_s[e];
            acc += htile[s * 32 + lane] * (dinv_s[s] * dn);
        }
        float v = tanhf(acc + bia);
        if (LAYER == 0)
            out[((size_t)g * NN + n) * C + c0 + lane] = v;
        else
            gacc += v;
    }
    if (LAYER == 1) {
        wsum[warp * 32 + lane] = gacc;
        __syncthreads();
        if (warp == 0) {
            float s = 0.f;
#pragma unroll
            for (int w = 0; w < 32; w++) s += wsum[w * 32 + lane];
            g_gvec[g * C + c0 + lane] = s;   // block exclusively owns this slot
        }
    }
}

// ---------------- qkv: one block per graph-row ----------------
__global__ void qkv_kernel(const float* __restrict__ in_w, const float* __restrict__ in_b) {
    int bi = blockIdx.x;
    int tid = threadIdx.x;       // 384 threads
    __shared__ float gr[C];
    if (tid < C) gr[tid] = g_gvec[bi * C + tid];
    __syncthreads();
    float acc = in_b[tid];
    const float* wr = in_w + (size_t)tid * C;
#pragma unroll 4
    for (int c = 0; c < C; c++) acc += gr[c] * wr[c];
    g_qkv[bi * 3 * C + tid] = acc;
}

// ---------------- attention + out-proj + MLP + LN + relu-sum ----------------
__device__ __forceinline__ float blksum128(float v, float* red) {
#pragma unroll
    for (int o = 16; o > 0; o >>= 1) v += __shfl_down_sync(0xffffffffu, v, o);
    if ((threadIdx.x & 31) == 0) red[threadIdx.x >> 5] = v;
    __syncthreads();
    float s = red[0] + red[1] + red[2] + red[3];
    __syncthreads();
    return s;
}

__global__ void tail_kernel(const float* __restrict__ out_w, const float* __restrict__ out_b,
                            const float* __restrict__ ln_g, const float* __restrict__ ln_b,
                            const float* __restrict__ mw1, const float* __restrict__ mb1,
                            const float* __restrict__ mw2, const float* __restrict__ mb2) {
    int bi = blockIdx.x;
    int tid = threadIdx.x;       // 128 threads
    __shared__ float kv[64 * C];
    __shared__ float qrow[C], sc[4 * 64], orow[C], o2row[C], hid[HIDN];
    __shared__ float red[4];

    for (int i = tid; i < 64 * C; i += 128) {
        int r = i >> 7, c = i & 127;
        kv[i] = g_qkv[r * 3 * C + C + c];
    }
    qrow[tid] = g_qkv[bi * 3 * C + tid];
    __syncthreads();

    for (int s = tid; s < 256; s += 128) {
        int h = s >> 6, k = s & 63;
        const float* kr = kv + k * C + h * 32;
        const float* qr = qrow + h * 32;
        float a = 0.f;
#pragma unroll
        for (int dd = 0; dd < 32; dd++) a += qr[dd] * kr[dd];
        sc[s] = a * 0.17677669529663687f;
    }
    __syncthreads();

    if (tid < 4) {
        float m = -1e30f;
        for (int k = 0; k < 64; k++) m = fmaxf(m, sc[tid * 64 + k]);
        float ssum = 0.f;
        for (int k = 0; k < 64; k++) { float e = expf(sc[tid * 64 + k] - m); sc[tid * 64 + k] = e; ssum += e; }
        float inv = 1.0f / ssum;
        for (int k = 0; k < 64; k++) sc[tid * 64 + k] *= inv;
    }
    __syncthreads();

    for (int i = tid; i < 64 * C; i += 128) {
        int r = i >> 7, c = i & 127;
        kv[i] = g_qkv[r * 3 * C + 2 * C + c];
    }
    __syncthreads();

    {
        int c = tid, h = c >> 5;
        float a = 0.f;
        for (int k = 0; k < 64; k++) a += sc[h * 64 + k] * kv[k * C + c];
        orow[c] = a;
    }
    __syncthreads();

    {
        int j = tid;
        float a = out_b[j];
        const float* wr = out_w + (size_t)j * C;
#pragma unroll 4
        for (int c = 0; c < C; c++) a += orow[c] * wr[c];
        o2row[j] = a;
    }
    __syncthreads();

    for (int j = tid; j < HIDN; j += 128) {
        float a = mb1[j];
        for (int c = 0; c < C; c++) a += o2row[c] * mw1[c * HIDN + j];
        hid[j] = fmaxf(a, 0.f);
    }
    __syncthreads();

    float y;
    {
        int c = tid;
        float a = mb2[c];
        for (int j = 0; j < HIDN; j++) a += hid[j] * mw2[j * C + c];
        y = o2row[c] + a;
    }
    float mu = blksum128(y, red) * (1.0f / 128.0f);
    float d = y - mu;
    float var = blksum128(d * d, red) * (1.0f / 128.0f);
    float yn = d * rsqrtf(var + 1e-5f) * ln_g[tid] + ln_b[tid];
    atomicAdd(&g_nrepr[tid], fmaxf(yn, 0.f));
}

__global__ void final_kernel(const float* __restrict__ lw, const float* __restrict__ lb,
                             float* __restrict__ out) {
    int tid = threadIdx.x;
    if (tid < NCLS) {
        float a = lb[tid];
        for (int c = 0; c < C; c++) a += g_nrepr[c] * lw[c * NCLS + tid];
        out[tid] = a;
    }
}

// ---------------- launch ----------------
extern "C" void kernel_launch(void* const* d_in, const int* in_sizes, int n_in,
                              void* d_out, int out_size) {
    const float* x     = (const float*)d_in[0];
    const int*   ei    = (const int*)d_in[1];
    const float* W0    = (const float*)d_in[2];
    const float* b0    = (const float*)d_in[3];
    const float* W1    = (const float*)d_in[4];
    const float* b1    = (const float*)d_in[5];
    const float* in_w  = (const float*)d_in[6];
    const float* in_b  = (const float*)d_in[7];
    const float* out_w = (const float*)d_in[8];
    const float* out_b = (const float*)d_in[9];
    const float* ln2_g = (const float*)d_in[10];
    const float* ln2_b = (const float*)d_in[11];
    const float* mw1   = (const float*)d_in[12];
    const float* mb1   = (const float*)d_in[13];
    const float* mw2   = (const float*)d_in[14];
    const float* mb2   = (const float*)d_in[15];
    const float* lw    = (const float*)d_in[16];
    const float* lb    = (const float*)d_in[17];
    float* out = (float*)d_out;

    float *bufA, *bufB;
    cudaGetSymbolAddress((void**)&bufA, g_bufA);
    cudaGetSymbolAddress((void**)&bufB, g_bufB);

    int gemm_smem = GEMM_SMEM_WORDS * 4;
    cudaFuncSetAttribute(gemm_tc_kernel, cudaFuncAttributeMaxDynamicSharedMemorySize, gemm_smem);
    cudaFuncSetAttribute(agg_kernel<0>, cudaFuncAttributeMaxDynamicSharedMemorySize, AGG_SMEM_BYTES);
    cudaFuncSetAttribute(agg_kernel<1>, cudaFuncAttributeMaxDynamicSharedMemorySize, AGG_SMEM_BYTES);

    prep_kernel<<<G, 1024>>>(ei);

    gemm_tc_kernel<<<(G * NN) / 64, 256, gemm_smem>>>(x, W0, bufA);
    agg_kernel<0><<<dim3(4, G), 1024, AGG_SMEM_BYTES>>>(bufA, bufB, b0);
    gemm_tc_kernel<<<(G * NN) / 64, 256, gemm_smem>>>(bufB, W1, bufA);
    agg_kernel<1><<<dim3(4, G), 1024, AGG_SMEM_BYTES>>>(bufA, nullptr, b1);

    qkv_kernel<<<G, 3 * C>>>(in_w, in_b);
    tail_kernel<<<G, C>>>(out_w, out_b, ln2_g, ln2_b, mw1, mb1, mw2, mb2);
    final_kernel<<<1, 32>>>(lw, lb, out);
}

// round 3
// speedup vs baseline: 1.1497x; 1.1497x over previous
#include <cuda_runtime.h>
#include <math.h>
#include <stdint.h>

#define G 64
#define NN 1000
#define EE 8192
#define C 128
#define HIDN 256
#define NCLS 2

// ---------------- scratch (device globals; no allocation allowed) ----------------
__device__ float g_bufA[(size_t)G * NN * C];   // 32.8 MB
__device__ float g_bufB[(size_t)G * NN * C];   // 32.8 MB
__device__ float g_dinv[G * NN];
__device__ int   g_rowptr[G * (NN + 1)];
__device__ int   g_csrsrc[G * EE];
__device__ float g_gvec[G * C];
__device__ float g_qkv[G * 3 * C];
__device__ float g_nrepr[C];

// ---------------- fused graph prep: one block per graph ----------------
__global__ void prep_kernel(const int* __restrict__ ei) {
    __shared__ int cnt[1024];
    __shared__ int cur[NN];
    int g = blockIdx.x;
    int t = threadIdx.x;          // 1024 threads
    const int* eb = ei + (size_t)g * 2 * EE;

    cnt[t] = 0;
    __syncthreads();
    for (int e = t; e < EE; e += 1024) atomicAdd(&cnt[eb[EE + e]], 1);
    __syncthreads();
    int d = cnt[t];
    __syncthreads();
    for (int off = 1; off < 1024; off <<= 1) {
        int v = (t >= off) ? cnt[t - off] : 0;
        __syncthreads();
        cnt[t] += v;
        __syncthreads();
    }
    if (t < NN) {
        g_rowptr[g * (NN + 1) + t + 1] = cnt[t];
        cur[t] = cnt[t] - d;
        g_dinv[g * NN + t] = rsqrtf((float)d + 1.0f);
    }
    if (t == 0) g_rowptr[g * (NN + 1)] = 0;
    if (t < C) g_gvec[g * C + t] = 0.0f;
    if (g == 0 && t < C) g_nrepr[t] = 0.0f;
    __syncthreads();
    for (int e = t; e < EE; e += 1024) {
        int src = eb[e];
        int dst = eb[EE + e];
        int pos = atomicAdd(&cur[dst], 1);
        g_csrsrc[g * EE + pos] = src;
    }
}

// ---------------- tf32 tensor-core GEMM (3xTF32): (64000 x 128) @ (128 x 128) ----------------
__device__ __forceinline__ uint32_t f2tf32(float f) {
    uint32_t u;
    asm("cvt.rna.tf32.f32 %0, %1;" : "=r"(u) : "f"(f));
    return u;
}

#define MMA_TF32(D,a0,a1,a2,a3,b0,b1)                                        \
    asm volatile(                                                            \
        "mma.sync.aligned.m16n8k8.row.col.f32.tf32.tf32.f32 "                \
        "{%0,%1,%2,%3}, {%4,%5,%6,%7}, {%8,%9}, {%0,%1,%2,%3};\n"            \
        : "+f"(D[0]), "+f"(D[1]), "+f"(D[2]), "+f"(D[3])                     \
        : "r"(a0), "r"(a1), "r"(a2), "r"(a3), "r"(b0), "r"(b1))

#define WPAD 132
// smem words: Xb + Xs (64*132 each) + W chunk (64*132 fp32)
#define GEMM_SMEM_WORDS (3 * 64 * WPAD)

__global__ void __launch_bounds__(256, 2)
gemm_tc_kernel(const float* __restrict__ X, const float* __restrict__ W,
               float* __restrict__ Y) {
    extern __shared__ uint32_t usm[];
    uint32_t* Xb = usm;                         // [64][132] tf32 big
    uint32_t* Xs = Xb + 64 * WPAD;              // [64][132] tf32 residual
    float* Ws = (float*)(Xs + 64 * WPAD);       // [64][132] raw W chunk

    int tid = threadIdx.x;
    int warp = tid >> 5, lane = tid & 31;
    int rowBase = blockIdx.x * 64;

    // stage X rows (tf32 big + residual)
    for (int i = tid; i < 64 * 128; i += 256) {
        int r = i >> 7, c = i & 127;
        float v = X[(size_t)(rowBase + r) * C + c];
        uint32_t b = f2tf32(v);
        Xb[r * WPAD + c] = b;
        Xs[r * WPAD + c] = f2tf32(v - __uint_as_float(b));
    }

    int grp = lane >> 2, tig = lane & 3;
    int cb = warp * 16;                         // this warp's 16 output cols

    float d[8][4];
#pragma unroll
    for (int i = 0; i < 8; i++)
#pragma unroll
        for (int j = 0; j < 4; j++) d[i][j] = 0.0f;

    for (int kc = 0; kc < 2; kc++) {
        __syncthreads();   // (kc=0: after X stage; kc=1: before Ws overwrite)
        for (int i = tid; i < 64 * 128; i += 256) {
            int r = i >> 7, c = i & 127;
            Ws[r * WPAD + c] = W[(kc * 64 + r) * 128 + c];
        }
        __syncthreads();

        // A = W^T fragments for this k-chunk (8 k-steps, big + small)
        uint32_t ab[8][4], asm_[8][4];
#pragma unroll
        for (int ks = 0; ks < 8; ks++) {
            int k0 = 8 * ks + tig;
#pragma unroll
            for (int p = 0; p < 4; p++) {
                int kk = k0 + ((p >> 1) << 2);
                int cc = cb + grp + ((p & 1) << 3);
                float v = Ws[kk * WPAD + cc];
                uint32_t b = f2tf32(v);
                ab[ks][p] = b;
                asm_[ks][p] = f2tf32(v - __uint_as_float(b));
            }
        }

#pragma unroll
        for (int rt = 0; rt < 8; rt++) {
            int xrow = (rt * 8 + grp) * WPAD + kc * 64;
#pragma unroll
            for (int ks = 0; ks < 8; ks++) {
                uint32_t bb0 = Xb[xrow + 8 * ks + tig];
                uint32_t bb1 = Xb[xrow + 8 * ks + tig + 4];
                uint32_t bs0 = Xs[xrow + 8 * ks + tig];
                uint32_t bs1 = Xs[xrow + 8 * ks + tig + 4];
                MMA_TF32(d[rt], ab[ks][0], ab[ks][1], ab[ks][2], ab[ks][3], bb0, bb1);
                MMA_TF32(d[rt], asm_[ks][0], asm_[ks][1], asm_[ks][2], asm_[ks][3], bb0, bb1);
                MMA_TF32(d[rt], ab[ks][0], ab[ks][1], ab[ks][2], ab[ks][3], bs0, bs1);
            }
        }
    }

#pragma unroll
    for (int rt = 0; rt < 8; rt++) {
        int r0 = rowBase + rt * 8 + 2 * tig;
        Y[(size_t)r0 * C + cb + grp] = d[rt][0];
        Y[(size_t)(r0 + 1) * C + cb + grp] = d[rt][1];
        Y[(size_t)r0 * C + cb + grp + 8] = d[rt][2];
        Y[(size_t)(r0 + 1) * C + cb + grp + 8] = d[rt][3];
    }
}

// ---------------- aggregation: global/L2 gather, high occupancy ----------------
__device__ __forceinline__ float fast_tanh(float x) {
    float r;
    asm("tanh.approx.f32 %0, %1;" : "=f"(r) : "f"(x));
    return r;
}

// grid: (4 col-chunks, G graphs, 8 node-slices of 125), 256 threads (warp = node)
template <int LAYER>
__global__ void __launch_bounds__(256)
agg_kernel(const float* __restrict__ h, float* __restrict__ out,
           const float* __restrict__ bias) {
    int g = blockIdx.y;
    int c0 = blockIdx.x * 32;
    int n0 = blockIdx.z * 125;
    int warp = threadIdx.x >> 5, lane = threadIdx.x & 31;
    const float* hb = h + (size_t)g * NN * C + c0;
    const int* rp = g_rowptr + g * (NN + 1);
    const int* srcs = g_csrsrc + g * EE;
    const float* dinv = g_dinv + g * NN;
    float bia = bias[c0 + lane];

    float gacc = 0.0f;
    for (int n = n0 + warp; n < n0 + 125; n += 8) {
        int st = __ldg(&rp[n]);
        int en = __ldg(&rp[n + 1]);
        float dn = dinv[n];
        float acc = hb[(size_t)n * C + lane] * (dn * dn);
        for (int e = st; e < en; e++) {
            int s = __ldg(&srcs[e]);
            acc += hb[(size_t)s * C + lane] * (__ldg(&dinv[s]) * dn);
        }
        float v = fast_tanh(acc + bia);
        if (LAYER == 0)
            out[((size_t)g * NN + n) * C + c0 + lane] = v;
        else
            gacc += v;
    }
    if (LAYER == 1) {
        __shared__ float wsum[8][32];
        wsum[warp][lane] = gacc;
        __syncthreads();
        if (warp == 0) {
            float s = 0.f;
#pragma unroll
            for (int w = 0; w < 8; w++) s += wsum[w][lane];
            atomicAdd(&g_gvec[g * C + c0 + lane], s);
        }
    }
}

// ---------------- qkv: one block per graph-row ----------------
__global__ void qkv_kernel(const float* __restrict__ in_w, const float* __restrict__ in_b) {
    int bi = blockIdx.x;
    int tid = threadIdx.x;       // 384 threads
    __shared__ float gr[C];
    if (tid < C) gr[tid] = g_gvec[bi * C + tid];
    __syncthreads();
    float acc = in_b[tid];
    const float* wr = in_w + (size_t)tid * C;
#pragma unroll 4
    for (int c = 0; c < C; c++) acc += gr[c] * wr[c];
    g_qkv[bi * 3 * C + tid] = acc;
}

// ---------------- attention + out-proj + MLP + LN + relu-sum ----------------
__device__ __forceinline__ float blksum128(float v, float* red) {
#pragma unroll
    for (int o = 16; o > 0; o >>= 1) v += __shfl_down_sync(0xffffffffu, v, o);
    if ((threadIdx.x & 31) == 0) red[threadIdx.x >> 5] = v;
    __syncthreads();
    float s = red[0] + red[1] + red[2] + red[3];
    __syncthreads();
    return s;
}

__global__ void tail_kernel(const float* __restrict__ out_w, const float* __restrict__ out_b,
                            const float* __restrict__ ln_g, const float* __restrict__ ln_b,
                            const float* __restrict__ mw1, const float* __restrict__ mb1,
                            const float* __restrict__ mw2, const float* __restrict__ mb2) {
    int bi = blockIdx.x;
    int tid = threadIdx.x;       // 128 threads
    __shared__ float kv[64 * C];
    __shared__ float qrow[C], sc[4 * 64], orow[C], o2row[C], hid[HIDN];
    __shared__ float red[4];

    for (int i = tid; i < 64 * C; i += 128) {
        int r = i >> 7, c = i & 127;
        kv[i] = g_qkv[r * 3 * C + C + c];
    }
    qrow[tid] = g_qkv[bi * 3 * C + tid];
    __syncthreads();

    for (int s = tid; s < 256; s += 128) {
        int h = s >> 6, k = s & 63;
        const float* kr = kv + k * C + h * 32;
        const float* qr = qrow + h * 32;
        float a = 0.f;
#pragma unroll
        for (int dd = 0; dd < 32; dd++) a += qr[dd] * kr[dd];
        sc[s] = a * 0.17677669529663687f;
    }
    __syncthreads();

    if (tid < 4) {
        float m = -1e30f;
        for (int k = 0; k < 64; k++) m = fmaxf(m, sc[tid * 64 + k]);
        float ssum = 0.f;
        for (int k = 0; k < 64; k++) { float e = expf(sc[tid * 64 + k] - m); sc[tid * 64 + k] = e; ssum += e; }
        float inv = 1.0f / ssum;
        for (int k = 0; k < 64; k++) sc[tid * 64 + k] *= inv;
    }
    __syncthreads();

    for (int i = tid; i < 64 * C; i += 128) {
        int r = i >> 7, c = i & 127;
        kv[i] = g_qkv[r * 3 * C + 2 * C + c];
    }
    __syncthreads();

    {
        int c = tid, h = c >> 5;
        float a = 0.f;
        for (int k = 0; k < 64; k++) a += sc[h * 64 + k] * kv[k * C + c];
        orow[c] = a;
    }
    __syncthreads();

    {
        int j = tid;
        float a = out_b[j];
        const float* wr = out_w + (size_t)j * C;
#pragma unroll 4
        for (int c = 0; c < C; c++) a += orow[c] * wr[c];
        o2row[j] = a;
    }
    __syncthreads();

    for (int j = tid; j < HIDN; j += 128) {
        float a = mb1[j];
        for (int c = 0; c < C; c++) a += o2row[c] * mw1[c * HIDN + j];
        hid[j] = fmaxf(a, 0.f);
    }
    __syncthreads();

    float y;
    {
        int c = tid;
        float a = mb2[c];
        for (int j = 0; j < HIDN; j++) a += hid[j] * mw2[j * C + c];
        y = o2row[c] + a;
    }
    float mu = blksum128(y, red) * (1.0f / 128.0f);
    float d = y - mu;
    float var = blksum128(d * d, red) * (1.0f / 128.0f);
    float yn = d * rsqrtf(var + 1e-5f) * ln_g[tid] + ln_b[tid];
    atomicAdd(&g_nrepr[tid], fmaxf(yn, 0.f));
}

__global__ void final_kernel(const float* __restrict__ lw, const float* __restrict__ lb,
                             float* __restrict__ out) {
    int tid = threadIdx.x;
    if (tid < NCLS) {
        float a = lb[tid];
        for (int c = 0; c < C; c++) a += g_nrepr[c] * lw[c * NCLS + tid];
        out[tid] = a;
    }
}

// ---------------- launch ----------------
extern "C" void kernel_launch(void* const* d_in, const int* in_sizes, int n_in,
                              void* d_out, int out_size) {
    const float* x     = (const float*)d_in[0];
    const int*   ei    = (const int*)d_in[1];
    const float* W0    = (const float*)d_in[2];
    const float* b0    = (const float*)d_in[3];
    const float* W1    = (const float*)d_in[4];
    const float* b1    = (const float*)d_in[5];
    const float* in_w  = (const float*)d_in[6];
    const float* in_b  = (const float*)d_in[7];
    const float* out_w = (const float*)d_in[8];
    const float* out_b = (const float*)d_in[9];
    const float* ln2_g = (const float*)d_in[10];
    const float* ln2_b = (const float*)d_in[11];
    const float* mw1   = (const float*)d_in[12];
    const float* mb1   = (const float*)d_in[13];
    const float* mw2   = (const float*)d_in[14];
    const float* mb2   = (const float*)d_in[15];
    const float* lw    = (const float*)d_in[16];
    const float* lb    = (const float*)d_in[17];
    float* out = (float*)d_out;

    float *bufA, *bufB;
    cudaGetSymbolAddress((void**)&bufA, g_bufA);
    cudaGetSymbolAddress((void**)&bufB, g_bufB);

    int gemm_smem = GEMM_SMEM_WORDS * 4;
    cudaFuncSetAttribute(gemm_tc_kernel, cudaFuncAttributeMaxDynamicSharedMemorySize, gemm_smem);

    prep_kernel<<<G, 1024>>>(ei);

    gemm_tc_kernel<<<(G * NN) / 64, 256, gemm_smem>>>(x, W0, bufA);
    agg_kernel<0><<<dim3(4, G, 8), 256>>>(bufA, bufB, b0);
    gemm_tc_kernel<<<(G * NN) / 64, 256, gemm_smem>>>(bufB, W1, bufA);
    agg_kernel<1><<<dim3(4, G, 8), 256>>>(bufA, nullptr, b1);

    qkv_kernel<<<G, 3 * C>>>(in_w, in_b);
    tail_kernel<<<G, C>>>(out_w, out_b, ln2_g, ln2_b, mw1, mb1, mw2, mb2);
    final_kernel<<<1, 32>>>(lw, lb, out);
}

// round 4
// speedup vs baseline: 1.2058x; 1.0488x over previous
#include <cuda_runtime.h>
#include <math.h>
#include <stdint.h>

#define G 64
#define NN 1000
#define EE 8192
#define C 128
#define HIDN 256
#define NCLS 2

// ---------------- scratch (device globals; no allocation allowed) ----------------
__device__ float g_bufA[(size_t)G * NN * C];   // 32.8 MB
__device__ float g_bufB[(size_t)G * NN * C];   // 32.8 MB
__device__ float g_dinv[G * NN];
__device__ int   g_rowptr[G * (NN + 1)];
__device__ int   g_csrsrc[G * EE];
__device__ float g_gvec[G * C];
__device__ float g_qkv[G * 3 * C];
__device__ float g_nrepr[C];
// W fragments in per-thread MMA layout: [layer][warp*16+ks][lane] -> float4
__device__ float4 g_wfB[2][4096];
__device__ float4 g_wfS[2][4096];

// ---------------- fused graph prep: one block per graph ----------------
__global__ void prep_kernel(const int* __restrict__ ei) {
    __shared__ int cnt[1024];
    __shared__ int cur[NN];
    int g = blockIdx.x;
    int t = threadIdx.x;          // 1024 threads
    const int* eb = ei + (size_t)g * 2 * EE;

    cnt[t] = 0;
    __syncthreads();
    for (int e = t; e < EE; e += 1024) atomicAdd(&cnt[eb[EE + e]], 1);
    __syncthreads();
    int d = cnt[t];
    __syncthreads();
    for (int off = 1; off < 1024; off <<= 1) {
        int v = (t >= off) ? cnt[t - off] : 0;
        __syncthreads();
        cnt[t] += v;
        __syncthreads();
    }
    if (t < NN) {
        g_rowptr[g * (NN + 1) + t + 1] = cnt[t];
        cur[t] = cnt[t] - d;
        g_dinv[g * NN + t] = rsqrtf((float)d + 1.0f);
    }
    if (t == 0) g_rowptr[g * (NN + 1)] = 0;
    if (t < C) g_gvec[g * C + t] = 0.0f;
    if (g == 0 && t < C) g_nrepr[t] = 0.0f;
    __syncthreads();
    for (int e = t; e < EE; e += 1024) {
        int src = eb[e];
        int dst = eb[EE + e];
        int pos = atomicAdd(&cur[dst], 1);
        g_csrsrc[g * EE + pos] = src;
    }
}

// ---------------- tf32 helpers ----------------
__device__ __forceinline__ uint32_t f2tf32(float f) {
    uint32_t u;
    asm("cvt.rna.tf32.f32 %0, %1;" : "=r"(u) : "f"(f));
    return u;
}

#define MMA_TF32(D,a0,a1,a2,a3,b0,b1)                                        \
    asm volatile(                                                            \
        "mma.sync.aligned.m16n8k8.row.col.f32.tf32.tf32.f32 "                \
        "{%0,%1,%2,%3}, {%4,%5,%6,%7}, {%8,%9}, {%0,%1,%2,%3};\n"            \
        : "+f"(D[0]), "+f"(D[1]), "+f"(D[2]), "+f"(D[3])                     \
        : "r"(a0), "r"(a1), "r"(a2), "r"(a3), "r"(b0), "r"(b1))

// ---------------- W fragment precompute: per-thread MMA layout ----------------
// idx = warp*512 + ks*32 + lane; p in 0..3: kk = 8*ks + tig + ((p>>1)<<2),
// cc = warp*16 + grp + ((p&1)<<3). Values tf32 big + residual.
__global__ void wfrag_kernel(const float* __restrict__ W0, const float* __restrict__ W1) {
    int layer = blockIdx.y;
    const float* W = layer ? W1 : W0;
    int idx = blockIdx.x * 256 + threadIdx.x;   // 0..4095
    int lane = idx & 31;
    int ks = (idx >> 5) & 15;
    int w = idx >> 9;
    int grp = lane >> 2, tig = lane & 3;
    float b[4], s[4];
#pragma unroll
    for (int p = 0; p < 4; p++) {
        int kk = 8 * ks + tig + ((p >> 1) << 2);
        int cc = w * 16 + grp + ((p & 1) << 3);
        float v = W[kk * 128 + cc];
        uint32_t big = f2tf32(v);
        b[p] = __uint_as_float(big);
        s[p] = __uint_as_float(f2tf32(v - __uint_as_float(big)));
    }
    g_wfB[layer][idx] = make_float4(b[0], b[1], b[2], b[3]);
    g_wfS[layer][idx] = make_float4(s[0], s[1], s[2], s[3]);
}

// ---------------- tf32 tensor-core GEMM (3xTF32): (64000 x 128) @ (128 x 128) ----------------
// X packed in smem as float4 {big(tig), big(tig+4), small(tig), small(tig+4)}
// per (row, ks, tig). Row stride 68 float4 (272 words, ==16 mod 32 banks -> conflict-free LDS.128).
#define XROW_F4 68
#define GEMM_SMEM_BYTES (64 * XROW_F4 * 16)

__global__ void __launch_bounds__(256, 3)
gemm_tc_kernel(const float* __restrict__ X,
               const float4* __restrict__ WfB, const float4* __restrict__ WfS,
               float* __restrict__ Y) {
    extern __shared__ uint32_t usm[];
    float4* Xq4 = (float4*)usm;

    int tid = threadIdx.x;
    int warp = tid >> 5, lane = tid & 31;
    int rowBase = blockIdx.x * 64;

    // stage X: convert to tf32 big + residual, packed layout
    for (int i = tid; i < 64 * 32; i += 256) {         // 2048 float4 loads
        int r = i >> 5;
        int c4 = i & 31;                               // 4 consecutive cols
        float4 v = ((const float4*)(X + (size_t)(rowBase + r) * C))[c4];
        int c = c4 * 4;
        int ks = c >> 3, tt = c & 7;                   // tt in {0,4}
        uint32_t* base = usm + r * (XROW_F4 * 4) + ks * 16 + (tt >> 2);
        float vv[4] = {v.x, v.y, v.z, v.w};
#pragma unroll
        for (int j = 0; j < 4; j++) {
            uint32_t big = f2tf32(vv[j]);
            base[j * 4]     = big;
            base[j * 4 + 2] = f2tf32(vv[j] - __uint_as_float(big));
        }
    }
    __syncthreads();

    int grp = lane >> 2, tig = lane & 3;
    int cb = warp * 16;

    float d[8][4];
#pragma unroll
    for (int i = 0; i < 8; i++)
#pragma unroll
        for (int j = 0; j < 4; j++) d[i][j] = 0.0f;

    const float4* wb = WfB + warp * 512 + lane;
    const float4* ws = WfS + warp * 512 + lane;

#pragma unroll
    for (int ks = 0; ks < 16; ks++) {
        float4 A = __ldg(wb + ks * 32);
        float4 S = __ldg(ws + ks * 32);
        uint32_t a0 = __float_as_uint(A.x), a1 = __float_as_uint(A.y),
                 a2 = __float_as_uint(A.z), a3 = __float_as_uint(A.w);
        uint32_t s0 = __float_as_uint(S.x), s1 = __float_as_uint(S.y),
                 s2 = __float_as_uint(S.z), s3 = __float_as_uint(S.w);
#pragma unroll
        for (int rt = 0; rt < 8; rt++) {
            float4 xq = Xq4[(rt * 8 + grp) * XROW_F4 + ks * 4 + tig];
            uint32_t bb0 = __float_as_uint(xq.x), bb1 = __float_as_uint(xq.y);
            uint32_t bs0 = __float_as_uint(xq.z), bs1 = __float_as_uint(xq.w);
            MMA_TF32(d[rt], a0, a1, a2, a3, bb0, bb1);
            MMA_TF32(d[rt], s0, s1, s2, s3, bb0, bb1);
            MMA_TF32(d[rt], a0, a1, a2, a3, bs0, bs1);
        }
    }

#pragma unroll
    for (int rt = 0; rt < 8; rt++) {
        int r0 = rowBase + rt * 8 + 2 * tig;
        Y[(size_t)r0 * C + cb + grp] = d[rt][0];
        Y[(size_t)(r0 + 1) * C + cb + grp] = d[rt][1];
        Y[(size_t)r0 * C + cb + grp + 8] = d[rt][2];
        Y[(size_t)(r0 + 1) * C + cb + grp + 8] = d[rt][3];
    }
}

// ---------------- aggregation: global/L2 gather, high occupancy ----------------
__device__ __forceinline__ float fast_tanh(float x) {
    float r;
    asm("tanh.approx.f32 %0, %1;" : "=f"(r) : "f"(x));
    return r;
}

template <int LAYER>
__global__ void __launch_bounds__(256)
agg_kernel(const float* __restrict__ h, float* __restrict__ out,
           const float* __restrict__ bias) {
    int g = blockIdx.y;
    int c0 = blockIdx.x * 32;
    int n0 = blockIdx.z * 125;
    int warp = threadIdx.x >> 5, lane = threadIdx.x & 31;
    const float* hb = h + (size_t)g * NN * C + c0;
    const int* rp = g_rowptr + g * (NN + 1);
    const int* srcs = g_csrsrc + g * EE;
    const float* dinv = g_dinv + g * NN;
    float bia = bias[c0 + lane];

    float gacc = 0.0f;
    for (int n = n0 + warp; n < n0 + 125; n += 8) {
        int st = __ldg(&rp[n]);
        int en = __ldg(&rp[n + 1]);
        float dn = dinv[n];
        float acc = hb[(size_t)n * C + lane] * (dn * dn);
        for (int e = st; e < en; e++) {
            int s = __ldg(&srcs[e]);
            acc += hb[(size_t)s * C + lane] * (__ldg(&dinv[s]) * dn);
        }
        float v = fast_tanh(acc + bia);
        if (LAYER == 0)
            out[((size_t)g * NN + n) * C + c0 + lane] = v;
        else
            gacc += v;
    }
    if (LAYER == 1) {
        __shared__ float wsum[8][32];
        wsum[warp][lane] = gacc;
        __syncthreads();
        if (warp == 0) {
            float s = 0.f;
#pragma unroll
            for (int w = 0; w < 8; w++) s += wsum[w][lane];
            atomicAdd(&g_gvec[g * C + c0 + lane], s);
        }
    }
}

// ---------------- qkv: one block per graph-row ----------------
__global__ void qkv_kernel(const float* __restrict__ in_w, const float* __restrict__ in_b) {
    int bi = blockIdx.x;
    int tid = threadIdx.x;       // 384 threads
    __shared__ float gr[C];
    if (tid < C) gr[tid] = g_gvec[bi * C + tid];
    __syncthreads();
    float acc = in_b[tid];
    const float* wr = in_w + (size_t)tid * C;
#pragma unroll 4
    for (int c = 0; c < C; c++) acc += gr[c] * wr[c];
    g_qkv[bi * 3 * C + tid] = acc;
}

// ---------------- attention + out-proj + MLP + LN + relu-sum ----------------
__device__ __forceinline__ float blksum128(float v, float* red) {
#pragma unroll
    for (int o = 16; o > 0; o >>= 1) v += __shfl_down_sync(0xffffffffu, v, o);
    if ((threadIdx.x & 31) == 0) red[threadIdx.x >> 5] = v;
    __syncthreads();
    float s = red[0] + red[1] + red[2] + red[3];
    __syncthreads();
    return s;
}

__global__ void tail_kernel(const float* __restrict__ out_w, const float* __restrict__ out_b,
                            const float* __restrict__ ln_g, const float* __restrict__ ln_b,
                            const float* __restrict__ mw1, const float* __restrict__ mb1,
                            const float* __restrict__ mw2, const float* __restrict__ mb2) {
    int bi = blockIdx.x;
    int tid = threadIdx.x;       // 128 threads
    __shared__ float kv[64 * C];
    __shared__ float qrow[C], sc[4 * 64], orow[C], o2row[C], hid[HIDN];
    __shared__ float red[4];

    for (int i = tid; i < 64 * C; i += 128) {
        int r = i >> 7, c = i & 127;
        kv[i] = g_qkv[r * 3 * C + C + c];
    }
    qrow[tid] = g_qkv[bi * 3 * C + tid];
    __syncthreads();

    for (int s = tid; s < 256; s += 128) {
        int h = s >> 6, k = s & 63;
        const float* kr = kv + k * C + h * 32;
        const float* qr = qrow + h * 32;
        float a = 0.f;
#pragma unroll
        for (int dd = 0; dd < 32; dd++) a += qr[dd] * kr[dd];
        sc[s] = a * 0.17677669529663687f;
    }
    __syncthreads();

    if (tid < 4) {
        float m = -1e30f;
        for (int k = 0; k < 64; k++) m = fmaxf(m, sc[tid * 64 + k]);
        float ssum = 0.f;
        for (int k = 0; k < 64; k++) { float e = expf(sc[tid * 64 + k] - m); sc[tid * 64 + k] = e; ssum += e; }
        float inv = 1.0f / ssum;
        for (int k = 0; k < 64; k++) sc[tid * 64 + k] *= inv;
    }
    __syncthreads();

    for (int i = tid; i < 64 * C; i += 128) {
        int r = i >> 7, c = i & 127;
        kv[i] = g_qkv[r * 3 * C + 2 * C + c];
    }
    __syncthreads();

    {
        int c = tid, h = c >> 5;
        float a = 0.f;
        for (int k = 0; k < 64; k++) a += sc[h * 64 + k] * kv[k * C + c];
        orow[c] = a;
    }
    __syncthreads();

    {
        int j = tid;
        float a = out_b[j];
        const float* wr = out_w + (size_t)j * C;
#pragma unroll 4
        for (int c = 0; c < C; c++) a += orow[c] * wr[c];
        o2row[j] = a;
    }
    __syncthreads();

    for (int j = tid; j < HIDN; j += 128) {
        float a = mb1[j];
        for (int c = 0; c < C; c++) a += o2row[c] * mw1[c * HIDN + j];
        hid[j] = fmaxf(a, 0.f);
    }
    __syncthreads();

    float y;
    {
        int c = tid;
        float a = mb2[c];
        for (int j = 0; j < HIDN; j++) a += hid[j] * mw2[j * C + c];
        y = o2row[c] + a;
    }
    float mu = blksum128(y, red) * (1.0f / 128.0f);
    float d = y - mu;
    float var = blksum128(d * d, red) * (1.0f / 128.0f);
    float yn = d * rsqrtf(var + 1e-5f) * ln_g[tid] + ln_b[tid];
    atomicAdd(&g_nrepr[tid], fmaxf(yn, 0.f));
}

__global__ void final_kernel(const float* __restrict__ lw, const float* __restrict__ lb,
                             float* __restrict__ out) {
    int tid = threadIdx.x;
    if (tid < NCLS) {
        float a = lb[tid];
        for (int c = 0; c < C; c++) a += g_nrepr[c] * lw[c * NCLS + tid];
        out[tid] = a;
    }
}

// ---------------- launch ----------------
extern "C" void kernel_launch(void* const* d_in, const int* in_sizes, int n_in,
                              void* d_out, int out_size) {
    const float* x     = (const float*)d_in[0];
    const int*   ei    = (const int*)d_in[1];
    const float* W0    = (const float*)d_in[2];
    const float* b0    = (const float*)d_in[3];
    const float* W1    = (const float*)d_in[4];
    const float* b1    = (const float*)d_in[5];
    const float* in_w  = (const float*)d_in[6];
    const float* in_b  = (const float*)d_in[7];
    const float* out_w = (const float*)d_in[8];
    const float* out_b = (const float*)d_in[9];
    const float* ln2_g = (const float*)d_in[10];
    const float* ln2_b = (const float*)d_in[11];
    const float* mw1   = (const float*)d_in[12];
    const float* mb1   = (const float*)d_in[13];
    const float* mw2   = (const float*)d_in[14];
    const float* mb2   = (const float*)d_in[15];
    const float* lw    = (const float*)d_in[16];
    const float* lb    = (const float*)d_in[17];
    float* out = (float*)d_out;

    float *bufA, *bufB;
    cudaGetSymbolAddress((void**)&bufA, g_bufA);
    cudaGetSymbolAddress((void**)&bufB, g_bufB);
    float4 *wfB, *wfS;
    cudaGetSymbolAddress((void**)&wfB, g_wfB);
    cudaGetSymbolAddress((void**)&wfS, g_wfS);

    cudaFuncSetAttribute(gemm_tc_kernel, cudaFuncAttributeMaxDynamicSharedMemorySize, GEMM_SMEM_BYTES);

    wfrag_kernel<<<dim3(16, 2), 256>>>(W0, W1);
    prep_kernel<<<G, 1024>>>(ei);

    gemm_tc_kernel<<<(G * NN) / 64, 256, GEMM_SMEM_BYTES>>>(x, wfB, wfS, bufA);
    agg_kernel<0><<<dim3(4, G, 8), 256>>>(bufA, bufB, b0);
    gemm_tc_kernel<<<(G * NN) / 64, 256, GEMM_SMEM_BYTES>>>(bufB, wfB + 4096, wfS + 4096, bufA);
    agg_kernel<1><<<dim3(4, G, 8), 256>>>(bufA, nullptr, b1);

    qkv_kernel<<<G, 3 * C>>>(in_w, in_b);
    tail_kernel<<<G, C>>>(out_w, out_b, ln2_g, ln2_b, mw1, mb1, mw2, mb2);
    final_kernel<<<1, 32>>>(lw, lb, out);
}

// round 5
// speedup vs baseline: 1.4949x; 1.2397x over previous
#include <cuda_runtime.h>
#include <math.h>
#include <stdint.h>

#define G 64
#define NN 1000
#define EE 8192
#define C 128
#define HIDN 256
#define NCLS 2

// ---------------- scratch (device globals; no allocation allowed) ----------------
__device__ float g_bufA[(size_t)G * NN * C];   // 32.8 MB
__device__ float g_bufB[(size_t)G * NN * C];   // 32.8 MB
__device__ float g_dinv[G * NN];
__device__ int   g_rowptr[G * (NN + 1)];
__device__ float2 g_edge[G * EE];              // {src_as_float, dinv[src]*dinv[dst]}
__device__ float g_gvec[G * C];
__device__ float g_qkv[G * 3 * C];
__device__ float g_nrepr[C];
// W fragments in per-thread MMA layout: [layer][warp*16+ks][lane] -> float4
__device__ float4 g_wfB[2][4096];
__device__ float4 g_wfS[2][4096];

// ---------------- fused graph prep: one block per graph ----------------
__global__ void prep_kernel(const int* __restrict__ ei) {
    __shared__ int cnt[1024];
    __shared__ int cur[NN];
    __shared__ float sdinv[NN];
    int g = blockIdx.x;
    int t = threadIdx.x;          // 1024 threads
    const int* eb = ei + (size_t)g * 2 * EE;

    cnt[t] = 0;
    __syncthreads();
    for (int e = t; e < EE; e += 1024) atomicAdd(&cnt[eb[EE + e]], 1);
    __syncthreads();
    int d = cnt[t];
    __syncthreads();
    for (int off = 1; off < 1024; off <<= 1) {
        int v = (t >= off) ? cnt[t - off] : 0;
        __syncthreads();
        cnt[t] += v;
        __syncthreads();
    }
    if (t < NN) {
        g_rowptr[g * (NN + 1) + t + 1] = cnt[t];
        cur[t] = cnt[t] - d;
        float di = rsqrtf((float)d + 1.0f);
        sdinv[t] = di;
        g_dinv[g * NN + t] = di;
    }
    if (t == 0) g_rowptr[g * (NN + 1)] = 0;
    if (t < C) g_gvec[g * C + t] = 0.0f;
    if (g == 0 && t < C) g_nrepr[t] = 0.0f;
    __syncthreads();
    for (int e = t; e < EE; e += 1024) {
        int src = eb[e];
        int dst = eb[EE + e];
        int pos = atomicAdd(&cur[dst], 1);
        g_edge[g * EE + pos] = make_float2(__int_as_float(src), sdinv[src] * sdinv[dst]);
    }
}

// ---------------- tf32 helpers ----------------
__device__ __forceinline__ uint32_t f2tf32(float f) {
    uint32_t u;
    asm("cvt.rna.tf32.f32 %0, %1;" : "=r"(u) : "f"(f));
    return u;
}

#define MMA_TF32(D,a0,a1,a2,a3,b0,b1)                                        \
    asm volatile(                                                            \
        "mma.sync.aligned.m16n8k8.row.col.f32.tf32.tf32.f32 "                \
        "{%0,%1,%2,%3}, {%4,%5,%6,%7}, {%8,%9}, {%0,%1,%2,%3};\n"            \
        : "+f"(D[0]), "+f"(D[1]), "+f"(D[2]), "+f"(D[3])                     \
        : "r"(a0), "r"(a1), "r"(a2), "r"(a3), "r"(b0), "r"(b1))

// ---------------- W fragment precompute: per-thread MMA layout ----------------
__global__ void wfrag_kernel(const float* __restrict__ W0, const float* __restrict__ W1) {
    int layer = blockIdx.y;
    const float* W = layer ? W1 : W0;
    int idx = blockIdx.x * 256 + threadIdx.x;   // 0..4095
    int lane = idx & 31;
    int ks = (idx >> 5) & 15;
    int w = idx >> 9;
    int grp = lane >> 2, tig = lane & 3;
    float b[4], s[4];
#pragma unroll
    for (int p = 0; p < 4; p++) {
        int kk = 8 * ks + tig + ((p >> 1) << 2);
        int cc = w * 16 + grp + ((p & 1) << 3);
        float v = W[kk * 128 + cc];
        uint32_t big = f2tf32(v);
        b[p] = __uint_as_float(big);
        s[p] = __uint_as_float(f2tf32(v - __uint_as_float(big)));
    }
    g_wfB[layer][idx] = make_float4(b[0], b[1], b[2], b[3]);
    g_wfS[layer][idx] = make_float4(s[0], s[1], s[2], s[3]);
}

// ---------------- tf32 tensor-core GEMM (3xTF32): (64000 x 128) @ (128 x 128) ----------------
#define XROW_F4 68
#define GEMM_SMEM_BYTES (64 * XROW_F4 * 16)

__global__ void __launch_bounds__(256, 3)
gemm_tc_kernel(const float* __restrict__ X,
               const float4* __restrict__ WfB, const float4* __restrict__ WfS,
               float* __restrict__ Y) {
    extern __shared__ uint32_t usm[];
    float4* Xq4 = (float4*)usm;

    int tid = threadIdx.x;
    int warp = tid >> 5, lane = tid & 31;
    int rowBase = blockIdx.x * 64;

    for (int i = tid; i < 64 * 32; i += 256) {
        int r = i >> 5;
        int c4 = i & 31;
        float4 v = ((const float4*)(X + (size_t)(rowBase + r) * C))[c4];
        int c = c4 * 4;
        int ks = c >> 3, tt = c & 7;
        uint32_t* base = usm + r * (XROW_F4 * 4) + ks * 16 + (tt >> 2);
        float vv[4] = {v.x, v.y, v.z, v.w};
#pragma unroll
        for (int j = 0; j < 4; j++) {
            uint32_t big = f2tf32(vv[j]);
            base[j * 4]     = big;
            base[j * 4 + 2] = f2tf32(vv[j] - __uint_as_float(big));
        }
    }
    __syncthreads();

    int grp = lane >> 2, tig = lane & 3;
    int cb = warp * 16;

    float d[8][4];
#pragma unroll
    for (int i = 0; i < 8; i++)
#pragma unroll
        for (int j = 0; j < 4; j++) d[i][j] = 0.0f;

    const float4* wb = WfB + warp * 512 + lane;
    const float4* ws = WfS + warp * 512 + lane;

#pragma unroll
    for (int ks = 0; ks < 16; ks++) {
        float4 A = __ldg(wb + ks * 32);
        float4 S = __ldg(ws + ks * 32);
        uint32_t a0 = __float_as_uint(A.x), a1 = __float_as_uint(A.y),
                 a2 = __float_as_uint(A.z), a3 = __float_as_uint(A.w);
        uint32_t s0 = __float_as_uint(S.x), s1 = __float_as_uint(S.y),
                 s2 = __float_as_uint(S.z), s3 = __float_as_uint(S.w);
#pragma unroll
        for (int rt = 0; rt < 8; rt++) {
            float4 xq = Xq4[(rt * 8 + grp) * XROW_F4 + ks * 4 + tig];
            uint32_t bb0 = __float_as_uint(xq.x), bb1 = __float_as_uint(xq.y);
            uint32_t bs0 = __float_as_uint(xq.z), bs1 = __float_as_uint(xq.w);
            MMA_TF32(d[rt], a0, a1, a2, a3, bb0, bb1);
            MMA_TF32(d[rt], s0, s1, s2, s3, bb0, bb1);
            MMA_TF32(d[rt], a0, a1, a2, a3, bs0, bs1);
        }
    }

#pragma unroll
    for (int rt = 0; rt < 8; rt++) {
        int r0 = rowBase + rt * 8 + 2 * tig;
        Y[(size_t)r0 * C + cb + grp] = d[rt][0];
        Y[(size_t)(r0 + 1) * C + cb + grp] = d[rt][1];
        Y[(size_t)r0 * C + cb + grp + 8] = d[rt][2];
        Y[(size_t)(r0 + 1) * C + cb + grp + 8] = d[rt][3];
    }
}

// ---------------- aggregation: warp per node, lane = 4 cols, packed edges ----------------
__device__ __forceinline__ float fast_tanh(float x) {
    float r;
    asm("tanh.approx.f32 %0, %1;" : "=f"(r) : "f"(x));
    return r;
}

// grid: (125 node-slices, G); block 256 = 8 warps; warp handles one node
template <int LAYER>
__global__ void __launch_bounds__(256)
agg_kernel(const float* __restrict__ h, float* __restrict__ out,
           const float* __restrict__ bias) {
    int g = blockIdx.y;
    int warp = threadIdx.x >> 5, lane = threadIdx.x & 31;
    int n = blockIdx.x * 8 + warp;      // 0..999
    int col = lane * 4;

    const float* hb = h + (size_t)g * NN * C + col;
    const float2* ep = g_edge + g * EE;
    int st = __ldg(&g_rowptr[g * (NN + 1) + n]);
    int en = __ldg(&g_rowptr[g * (NN + 1) + n + 1]);
    float dn = __ldg(&g_dinv[g * NN + n]);
    float4 bia = *(const float4*)(bias + col);

    float4 self = *(const float4*)(hb + (size_t)n * C);
    float d2 = dn * dn;
    float4 acc;
    acc.x = self.x * d2 + bia.x;
    acc.y = self.y * d2 + bia.y;
    acc.z = self.z * d2 + bia.z;
    acc.w = self.w * d2 + bia.w;

    for (int e = st; e < en; e++) {
        float2 eg = __ldg(&ep[e]);
        int s = __float_as_int(eg.x);
        float w = eg.y;
        float4 hr = *(const float4*)(hb + (size_t)s * C);
        acc.x += hr.x * w;
        acc.y += hr.y * w;
        acc.z += hr.z * w;
        acc.w += hr.w * w;
    }
    acc.x = fast_tanh(acc.x);
    acc.y = fast_tanh(acc.y);
    acc.z = fast_tanh(acc.z);
    acc.w = fast_tanh(acc.w);

    if (LAYER == 0) {
        *(float4*)(out + ((size_t)g * NN + n) * C + col) = acc;
    } else {
        __shared__ float4 wsum[8][32];
        wsum[warp][lane] = acc;
        __syncthreads();
        if (warp == 0) {
            float4 s = wsum[0][lane];
#pragma unroll
            for (int w = 1; w < 8; w++) {
                float4 t = wsum[w][lane];
                s.x += t.x; s.y += t.y; s.z += t.z; s.w += t.w;
            }
            atomicAdd(&g_gvec[g * C + col], s.x);
            atomicAdd(&g_gvec[g * C + col + 1], s.y);
            atomicAdd(&g_gvec[g * C + col + 2], s.z);
            atomicAdd(&g_gvec[g * C + col + 3], s.w);
        }
    }
}

// ---------------- qkv: one block per graph-row ----------------
__global__ void qkv_kernel(const float* __restrict__ in_w, const float* __restrict__ in_b) {
    int bi = blockIdx.x;
    int tid = threadIdx.x;       // 384 threads
    __shared__ float gr[C];
    if (tid < C) gr[tid] = g_gvec[bi * C + tid];
    __syncthreads();
    float acc = in_b[tid];
    const float* wr = in_w + (size_t)tid * C;
#pragma unroll 4
    for (int c = 0; c < C; c++) acc += gr[c] * wr[c];
    g_qkv[bi * 3 * C + tid] = acc;
}

// ---------------- attention + out-proj + MLP + LN + relu-sum ----------------
__device__ __forceinline__ float blksum128(float v, float* red) {
#pragma unroll
    for (int o = 16; o > 0; o >>= 1) v += __shfl_down_sync(0xffffffffu, v, o);
    if ((threadIdx.x & 31) == 0) red[threadIdx.x >> 5] = v;
    __syncthreads();
    float s = red[0] + red[1] + red[2] + red[3];
    __syncthreads();
    return s;
}

__global__ void tail_kernel(const float* __restrict__ out_w, const float* __restrict__ out_b,
                            const float* __restrict__ ln_g, const float* __restrict__ ln_b,
                            const float* __restrict__ mw1, const float* __restrict__ mb1,
                            const float* __restrict__ mw2, const float* __restrict__ mb2) {
    int bi = blockIdx.x;
    int tid = threadIdx.x;       // 128 threads
    __shared__ float kv[64 * C];
    __shared__ float qrow[C], sc[4 * 64], orow[C], o2row[C], hid[HIDN];
    __shared__ float red[4];

    for (int i = tid; i < 64 * C; i += 128) {
        int r = i >> 7, c = i & 127;
        kv[i] = g_qkv[r * 3 * C + C + c];
    }
    qrow[tid] = g_qkv[bi * 3 * C + tid];
    __syncthreads();

    for (int s = tid; s < 256; s += 128) {
        int h = s >> 6, k = s & 63;
        const float* kr = kv + k * C + h * 32;
        const float* qr = qrow + h * 32;
        float a = 0.f;
#pragma unroll
        for (int dd = 0; dd < 32; dd++) a += qr[dd] * kr[dd];
        sc[s] = a * 0.17677669529663687f;
    }
    __syncthreads();

    if (tid < 4) {
        float m = -1e30f;
        for (int k = 0; k < 64; k++) m = fmaxf(m, sc[tid * 64 + k]);
        float ssum = 0.f;
        for (int k = 0; k < 64; k++) { float e = expf(sc[tid * 64 + k] - m); sc[tid * 64 + k] = e; ssum += e; }
        float inv = 1.0f / ssum;
        for (int k = 0; k < 64; k++) sc[tid * 64 + k] *= inv;
    }
    __syncthreads();

    for (int i = tid; i < 64 * C; i += 128) {
        int r = i >> 7, c = i & 127;
        kv[i] = g_qkv[r * 3 * C + 2 * C + c];
    }
    __syncthreads();

    {
        int c = tid, h = c >> 5;
        float a = 0.f;
        for (int k = 0; k < 64; k++) a += sc[h * 64 + k] * kv[k * C + c];
        orow[c] = a;
    }
    __syncthreads();

    {
        int j = tid;
        float a = out_b[j];
        const float* wr = out_w + (size_t)j * C;
#pragma unroll 4
        for (int c = 0; c < C; c++) a += orow[c] * wr[c];
        o2row[j] = a;
    }
    __syncthreads();

    for (int j = tid; j < HIDN; j += 128) {
        float a = mb1[j];
        for (int c = 0; c < C; c++) a += o2row[c] * mw1[c * HIDN + j];
        hid[j] = fmaxf(a, 0.f);
    }
    __syncthreads();

    float y;
    {
        int c = tid;
        float a = mb2[c];
        for (int j = 0; j < HIDN; j++) a += hid[j] * mw2[j * C + c];
        y = o2row[c] + a;
    }
    float mu = blksum128(y, red) * (1.0f / 128.0f);
    float d = y - mu;
    float var = blksum128(d * d, red) * (1.0f / 128.0f);
    float yn = d * rsqrtf(var + 1e-5f) * ln_g[tid] + ln_b[tid];
    atomicAdd(&g_nrepr[tid], fmaxf(yn, 0.f));
}

__global__ void final_kernel(const float* __restrict__ lw, const float* __restrict__ lb,
                             float* __restrict__ out) {
    int tid = threadIdx.x;
    if (tid < NCLS) {
        float a = lb[tid];
        for (int c = 0; c < C; c++) a += g_nrepr[c] * lw[c * NCLS + tid];
        out[tid] = a;
    }
}

// ---------------- launch ----------------
extern "C" void kernel_launch(void* const* d_in, const int* in_sizes, int n_in,
                              void* d_out, int out_size) {
    const float* x     = (const float*)d_in[0];
    const int*   ei    = (const int*)d_in[1];
    const float* W0    = (const float*)d_in[2];
    const float* b0    = (const float*)d_in[3];
    const float* W1    = (const float*)d_in[4];
    const float* b1    = (const float*)d_in[5];
    const float* in_w  = (const float*)d_in[6];
    const float* in_b  = (const float*)d_in[7];
    const float* out_w = (const float*)d_in[8];
    const float* out_b = (const float*)d_in[9];
    const float* ln2_g = (const float*)d_in[10];
    const float* ln2_b = (const float*)d_in[11];
    const float* mw1   = (const float*)d_in[12];
    const float* mb1   = (const float*)d_in[13];
    const float* mw2   = (const float*)d_in[14];
    const float* mb2   = (const float*)d_in[15];
    const float* lw    = (const float*)d_in[16];
    const float* lb    = (const float*)d_in[17];
    float* out = (float*)d_out;

    float *bufA, *bufB;
    cudaGetSymbolAddress((void**)&bufA, g_bufA);
    cudaGetSymbolAddress((void**)&bufB, g_bufB);
    float4 *wfB, *wfS;
    cudaGetSymbolAddress((void**)&wfB, g_wfB);
    cudaGetSymbolAddress((void**)&wfS, g_wfS);

    cudaFuncSetAttribute(gemm_tc_kernel, cudaFuncAttributeMaxDynamicSharedMemorySize, GEMM_SMEM_BYTES);

    wfrag_kernel<<<dim3(16, 2), 256>>>(W0, W1);
    prep_kernel<<<G, 1024>>>(ei);

    gemm_tc_kernel<<<(G * NN) / 64, 256, GEMM_SMEM_BYTES>>>(x, wfB, wfS, bufA);
    agg_kernel<0><<<dim3(125, G), 256>>>(bufA, bufB, b0);
    gemm_tc_kernel<<<(G * NN) / 64, 256, GEMM_SMEM_BYTES>>>(bufB, wfB + 4096, wfS + 4096, bufA);
    agg_kernel<1><<<dim3(125, G), 256>>>(bufA, nullptr, b1);

    qkv_kernel<<<G, 3 * C>>>(in_w, in_b);
    tail_kernel<<<G, C>>>(out_w, out_b, ln2_g, ln2_b, mw1, mb1, mw2, mb2);
    final_kernel<<<1, 32>>>(lw, lb, out);
}